// round 1
// baseline (speedup 1.0000x reference)
#include <cuda_runtime.h>
#include <cuda_bf16.h>
#include <math.h>

// Problem constants
#define T_LEN  4096
#define C_CH   64
#define B_SZ   64
#define NFREQ  2049            // T/2 + 1
#define FPAD   2052            // padded row for alignment
#define NCAND  6               // 2 * TOP_K
#define TOPK   3
#define LOG2T  12

// ---------------------------------------------------------------------------
// Scratch (device globals; no allocations allowed)
// ---------------------------------------------------------------------------
__device__ float g_part[B_SZ * 32 * FPAD];   // per-(batch, channel-pair) amplitude sums
__device__ float g_amps[B_SZ * FPAD];        // summed amplitudes per batch
__device__ int   g_topidx[B_SZ * NCAND];     // top-6 frequency indices per batch
__device__ float g_scores[B_SZ * NCAND];     // autocorr scores per candidate

// ---------------------------------------------------------------------------
// Kernel 1: packed complex FFT (2 real channels per FFT) + amplitude unpack
// grid = B*32 blocks, 256 threads. 48KB static smem.
// ---------------------------------------------------------------------------
__global__ __launch_bounds__(256) void fft_kernel(const float* __restrict__ x)
{
    __shared__ float2 z[T_LEN];     // 32 KB
    __shared__ float2 W[T_LEN / 2]; // 16 KB twiddles: W[j] = exp(-2*pi*i*j/T)

    const int tid  = threadIdx.x;
    const int b    = blockIdx.x >> 5;
    const int pair = blockIdx.x & 31;
    const int c0   = pair * 2;

    // Twiddle table
    for (int i = tid; i < T_LEN / 2; i += 256) {
        float ang = -6.283185307179586f * (float)i / (float)T_LEN;
        float s, c;
        sincosf(ang, &s, &c);
        W[i] = make_float2(c, s);
    }

    // Load bit-reversed: z[rev(t)] = (x[b,t,c0], x[b,t,c0+1])  -- contiguous float2
    const float* xb = x + (size_t)b * T_LEN * C_CH;
    for (int t = tid; t < T_LEN; t += 256) {
        int r = __brev((unsigned)t) >> (32 - LOG2T);
        const float2 v = *(const float2*)(xb + (size_t)t * C_CH + c0);
        z[r] = v;
    }
    __syncthreads();

    // 12 radix-2 stages
    for (int s = 1; s <= LOG2T; s++) {
        const int half = 1 << (s - 1);
        const int twsh = LOG2T - s;
        for (int j = tid; j < T_LEN / 2; j += 256) {
            const int group = j >> (s - 1);
            const int pos   = j & (half - 1);
            const int i0    = (group << s) + pos;
            const int i1    = i0 + half;
            const float2 w  = W[pos << twsh];
            const float2 a  = z[i0];
            const float2 bv = z[i1];
            const float tr = w.x * bv.x - w.y * bv.y;
            const float ti = w.x * bv.y + w.y * bv.x;
            z[i1] = make_float2(a.x - tr, a.y - ti);
            z[i0] = make_float2(a.x + tr, a.y + ti);
        }
        __syncthreads();
    }

    // Unpack Hermitian halves -> |X1[k]| + |X2[k]| for k in [0, 2048]
    float* out = g_part + (size_t)blockIdx.x * FPAD;
    for (int k = tid; k < NFREQ; k += 256) {
        const float2 a  = z[k];
        const float2 bm = z[(T_LEN - k) & (T_LEN - 1)];
        const float sr = 0.5f * (a.x + bm.x);
        const float si = 0.5f * (a.y - bm.y);
        const float dr = 0.5f * (a.x - bm.x);
        const float di = 0.5f * (a.y + bm.y);
        out[k] = sqrtf(sr * sr + si * si) + sqrtf(di * di + dr * dr);
    }
}

// ---------------------------------------------------------------------------
// Kernel 2: reduce 32 channel-pair partials per batch (deterministic order)
// ---------------------------------------------------------------------------
__global__ __launch_bounds__(256) void reduce_kernel()
{
    const int b = blockIdx.x;
    for (int k = threadIdx.x; k < NFREQ; k += 256) {
        float s = 0.0f;
        #pragma unroll 8
        for (int p = 0; p < 32; p++)
            s += g_part[(size_t)(b * 32 + p) * FPAD + k];
        g_amps[b * FPAD + k] = s;
    }
}

// ---------------------------------------------------------------------------
// Kernel 3: top-6 per batch (value desc, smaller index wins on ties)
// ---------------------------------------------------------------------------
__global__ __launch_bounds__(256) void topk_kernel()
{
    __shared__ float a[NFREQ];
    __shared__ float rv[256];
    __shared__ int   ri[256];

    const int b   = blockIdx.x;
    const int tid = threadIdx.x;

    for (int k = tid; k < NFREQ; k += 256) a[k] = g_amps[b * FPAD + k];
    __syncthreads();

    for (int sel = 0; sel < NCAND; sel++) {
        float bv = -1e30f;
        int   bi = 0x7fffffff;
        for (int k = tid; k < NFREQ; k += 256) {
            const float v = a[k];
            if (v > bv) { bv = v; bi = k; }   // ascending scan -> smallest idx on tie
        }
        rv[tid] = bv; ri[tid] = bi;
        __syncthreads();
        for (int s = 128; s > 0; s >>= 1) {
            if (tid < s) {
                const float v2 = rv[tid + s];
                const int   i2 = ri[tid + s];
                if (v2 > rv[tid] || (v2 == rv[tid] && i2 < ri[tid])) { rv[tid] = v2; ri[tid] = i2; }
            }
            __syncthreads();
        }
        if (tid == 0) {
            g_topidx[b * NCAND + sel] = ri[0];
            a[ri[0]] = -1e30f;
        }
        __syncthreads();
    }
}

// ---------------------------------------------------------------------------
// Kernel 4: autocorrelation score per (batch, candidate)
// grid = (NCAND, B). 256 threads. 32KB smem.
// ---------------------------------------------------------------------------
__global__ __launch_bounds__(256) void autocorr_kernel(const float* __restrict__ x)
{
    __shared__ float rs[T_LEN];
    __shared__ float qs[T_LEN];
    __shared__ float wacc[8];

    const int j   = blockIdx.x;
    const int b   = blockIdx.y;
    const int tid = threadIdx.x;

    const int idx = g_topidx[b * NCAND + j];
    const float pf = 4096.0f / (float)(idx + 1);
    int p = (int)floorf(pf);
    p = min(max(p, 2), T_LEN / 2);

    const float* xb = x + (size_t)b * T_LEN * C_CH;

    // r[t] = <x[t], x[t+p]> (0 when t+p >= T), q[t] = ||x[t]||^2
    for (int t = tid; t < T_LEN; t += 256) {
        const float4* A = (const float4*)(xb + (size_t)t * C_CH);
        float q = 0.0f, r = 0.0f;
        const int t2 = t + p;
        if (t2 < T_LEN) {
            const float4* Bv = (const float4*)(xb + (size_t)t2 * C_CH);
            #pragma unroll
            for (int i = 0; i < 16; i++) {
                const float4 av = A[i];
                const float4 bv = Bv[i];
                q += av.x * av.x + av.y * av.y + av.z * av.z + av.w * av.w;
                r += av.x * bv.x + av.y * bv.y + av.z * bv.z + av.w * bv.w;
            }
        } else {
            #pragma unroll
            for (int i = 0; i < 16; i++) {
                const float4 av = A[i];
                q += av.x * av.x + av.y * av.y + av.z * av.z + av.w * av.w;
            }
        }
        rs[t] = r;
        qs[t] = q;
    }
    __syncthreads();

    // Per-segment cosine similarities; warp w handles segments w, w+8, ...
    const int nper = T_LEN / p;
    const int nseg = nper - 1;           // >= 1 since p <= T/2
    const int warp = tid >> 5;
    const int lane = tid & 31;

    float wsum = 0.0f;
    for (int i = warp; i < nseg; i += 8) {
        const int s  = i * p;
        const int e  = s + p;
        const int e2 = e + p;
        float dot = 0.0f, na2 = 0.0f, nb2 = 0.0f;
        for (int t = s + lane; t < e; t += 32) { dot += rs[t]; na2 += qs[t]; }
        for (int t = e + lane; t < e2; t += 32) { nb2 += qs[t]; }
        #pragma unroll
        for (int o = 16; o > 0; o >>= 1) {
            dot += __shfl_down_sync(0xffffffffu, dot, o);
            na2 += __shfl_down_sync(0xffffffffu, na2, o);
            nb2 += __shfl_down_sync(0xffffffffu, nb2, o);
        }
        if (lane == 0) {
            const float na = sqrtf(fmaxf(na2, 0.0f));
            const float nb = sqrtf(fmaxf(nb2, 0.0f));
            wsum += dot / fmaxf(na * nb, 1e-8f);
        }
    }
    if (lane == 0) wacc[warp] = wsum;
    __syncthreads();
    if (tid == 0) {
        float total = 0.0f;
        #pragma unroll
        for (int w = 0; w < 8; w++) total += wacc[w];   // fixed order: deterministic
        g_scores[b * NCAND + j] = total / (float)nseg;
    }
}

// ---------------------------------------------------------------------------
// Kernel 5: final selection -> out = periods[64*3] ++ weights[64*3]
// ---------------------------------------------------------------------------
__global__ void select_kernel(float* __restrict__ out)
{
    const int b = blockIdx.x * blockDim.x + threadIdx.x;
    if (b >= B_SZ) return;

    int   pe[TOPK];
    float wt[TOPK];
    int cnt = 0;
    for (int j = 0; j < NCAND; j++) {
        const int idx = g_topidx[b * NCAND + j];
        const float pf  = 4096.0f / (float)(idx + 1);
        const float pfl = floorf(pf);
        const bool in_range     = (pf  >= 2.0f) && (pf  <= 2048.0f);
        const bool in_range_int = (pfl >= 2.0f) && (pfl <= 2048.0f);
        int pi = (int)pfl;
        pi = min(max(pi, 2), T_LEN / 2);
        const bool valid = in_range && in_range_int && (g_scores[b * NCAND + j] > 0.2f);
        if (valid && cnt < TOPK) { pe[cnt] = pi; wt[cnt] = 1.0f; cnt++; }
    }
    const int addp[3] = {1024, 1365, 2048};   // T//4, T//3, T//2 (int(T/1.5)=2730 > half)
    for (int j = cnt; j < TOPK; j++) {
        pe[j] = addp[min(j - cnt, 2)];
        wt[j] = 0.5f;
    }
    #pragma unroll
    for (int j = 0; j < TOPK; j++) {
        out[b * TOPK + j]                = (float)pe[j];
        out[B_SZ * TOPK + b * TOPK + j]  = wt[j];
    }
}

// ---------------------------------------------------------------------------
extern "C" void kernel_launch(void* const* d_in, const int* in_sizes, int n_in,
                              void* d_out, int out_size)
{
    const float* x  = (const float*)d_in[0];
    float* out = (float*)d_out;

    fft_kernel<<<B_SZ * 32, 256>>>(x);
    reduce_kernel<<<B_SZ, 256>>>();
    topk_kernel<<<B_SZ, 256>>>();
    autocorr_kernel<<<dim3(NCAND, B_SZ), 256>>>(x);
    select_kernel<<<1, 64>>>(out);
}

// round 3
// speedup vs baseline: 1.4502x; 1.4502x over previous
#include <cuda_runtime.h>
#include <cuda_bf16.h>
#include <math.h>

// Problem constants
#define T_LEN  4096
#define C_CH   64
#define B_SZ   64
#define NFREQ  2049            // T/2 + 1
#define FPAD   2052            // padded row for alignment
#define NCAND  6               // 2 * TOP_K
#define TOPK   3
#define LOG2T  12

// ---------------------------------------------------------------------------
// Scratch (device globals; no allocations allowed)
// ---------------------------------------------------------------------------
__device__ float g_part[B_SZ * 32 * FPAD];   // per-(batch, channel-pair) amplitude sums
__device__ float g_amps[B_SZ * FPAD];        // summed amplitudes per batch
__device__ int   g_topidx[B_SZ * NCAND];     // top-6 frequency indices per batch
__device__ float g_scores[B_SZ * NCAND];     // autocorr scores per candidate

__device__ __forceinline__ float2 cmul(float2 a, float2 b) {
    return make_float2(a.x * b.x - a.y * b.y, a.x * b.y + a.y * b.x);
}

// W table holds exp(-2*pi*i*e/4096) for e in [0, 2048). For e in [2048, 4096):
// W^e = -W^(e-2048).  (We only ever need e < 3072.)
__device__ __forceinline__ float2 twget(const float2* __restrict__ W, int e) {
    float2 w = W[e & 2047];
    if (e & 2048) { w.x = -w.x; w.y = -w.y; }
    return w;
}

// ---------------------------------------------------------------------------
// Kernel 1: packed complex radix-4 FFT (2 real channels per FFT) + unpack
// grid = B*32 blocks, 256 threads. 48KB static smem.
// ---------------------------------------------------------------------------
__global__ __launch_bounds__(256) void fft_kernel(const float* __restrict__ x)
{
    __shared__ float2 z[T_LEN];     // 32 KB
    __shared__ float2 W[T_LEN / 2]; // 16 KB twiddles

    const int tid  = threadIdx.x;
    const int b    = blockIdx.x >> 5;
    const int pair = blockIdx.x & 31;
    const int c0   = pair * 2;

    // Twiddle table
    for (int i = tid; i < T_LEN / 2; i += 256) {
        float ang = -6.283185307179586f * (float)i / (float)T_LEN;
        float s, c;
        sincosf(ang, &s, &c);
        W[i] = make_float2(c, s);
    }

    // Load with base-4 digit reversal (6 digits): z[rev4(t)] = (x[t,c0], x[t,c0+1])
    const float* xb = x + (size_t)b * T_LEN * C_CH;
    for (int t = tid; t < T_LEN; t += 256) {
        int tt = t, r = 0;
        #pragma unroll
        for (int i = 0; i < 6; i++) { r = (r << 2) | (tt & 3); tt >>= 2; }
        const float2 v = *(const float2*)(xb + (size_t)t * C_CH + c0);
        z[r] = v;
    }
    __syncthreads();

    // 6 radix-4 DIT stages
    #pragma unroll
    for (int s = 1; s <= 6; s++) {
        const int qtr  = 1 << (2 * (s - 1));
        const int twsh = 12 - 2 * s;
        #pragma unroll
        for (int u = 0; u < 4; u++) {
            const int j   = tid + u * 256;         // 1024 butterflies / stage
            const int grp = j >> (2 * (s - 1));
            const int pos = j & (qtr - 1);
            const int i0  = (grp << (2 * s)) + pos;
            const int tw  = pos << twsh;           // < 1024; 3*tw < 3072

            const float2 t0 = z[i0];
            const float2 t1 = cmul(z[i0 + qtr],     twget(W, tw));
            const float2 t2 = cmul(z[i0 + 2 * qtr], twget(W, 2 * tw));
            const float2 t3 = cmul(z[i0 + 3 * qtr], twget(W, 3 * tw));

            const float2 s02 = make_float2(t0.x + t2.x, t0.y + t2.y);
            const float2 d02 = make_float2(t0.x - t2.x, t0.y - t2.y);
            const float2 s13 = make_float2(t1.x + t3.x, t1.y + t3.y);
            const float2 d13 = make_float2(t1.x - t3.x, t1.y - t3.y);
            // -j * d13 = (d13.y, -d13.x)
            z[i0]           = make_float2(s02.x + s13.x, s02.y + s13.y);
            z[i0 + qtr]     = make_float2(d02.x + d13.y, d02.y - d13.x);
            z[i0 + 2 * qtr] = make_float2(s02.x - s13.x, s02.y - s13.y);
            z[i0 + 3 * qtr] = make_float2(d02.x - d13.y, d02.y + d13.x);
        }
        __syncthreads();
    }

    // Unpack Hermitian halves -> |X1[k]| + |X2[k]| for k in [0, 2048]
    float* out = g_part + (size_t)blockIdx.x * FPAD;
    for (int k = tid; k < NFREQ; k += 256) {
        const float2 a  = z[k];
        const float2 bm = z[(T_LEN - k) & (T_LEN - 1)];
        const float sr = 0.5f * (a.x + bm.x);
        const float si = 0.5f * (a.y - bm.y);
        const float dr = 0.5f * (a.x - bm.x);
        const float di = 0.5f * (a.y + bm.y);
        out[k] = sqrtf(sr * sr + si * si) + sqrtf(di * di + dr * dr);
    }
}

// ---------------------------------------------------------------------------
// Kernel 2: reduce 32 channel-pair partials per batch (deterministic order)
// ---------------------------------------------------------------------------
__global__ __launch_bounds__(256) void reduce_kernel()
{
    const int b = blockIdx.x;
    for (int k = threadIdx.x; k < NFREQ; k += 256) {
        float s = 0.0f;
        #pragma unroll 8
        for (int p = 0; p < 32; p++)
            s += g_part[(size_t)(b * 32 + p) * FPAD + k];
        g_amps[b * FPAD + k] = s;
    }
}

// ---------------------------------------------------------------------------
// Kernel 3: top-6 per batch (value desc, smaller index wins on ties)
// ---------------------------------------------------------------------------
__global__ __launch_bounds__(256) void topk_kernel()
{
    __shared__ float a[NFREQ];
    __shared__ float rv[256];
    __shared__ int   ri[256];

    const int b   = blockIdx.x;
    const int tid = threadIdx.x;

    for (int k = tid; k < NFREQ; k += 256) a[k] = g_amps[b * FPAD + k];
    __syncthreads();

    for (int sel = 0; sel < NCAND; sel++) {
        float bv = -1e30f;
        int   bi = 0x7fffffff;
        for (int k = tid; k < NFREQ; k += 256) {
            const float v = a[k];
            if (v > bv) { bv = v; bi = k; }   // ascending scan -> smallest idx on tie
        }
        rv[tid] = bv; ri[tid] = bi;
        __syncthreads();
        for (int s = 128; s > 0; s >>= 1) {
            if (tid < s) {
                const float v2 = rv[tid + s];
                const int   i2 = ri[tid + s];
                if (v2 > rv[tid] || (v2 == rv[tid] && i2 < ri[tid])) { rv[tid] = v2; ri[tid] = i2; }
            }
            __syncthreads();
        }
        if (tid == 0) {
            g_topidx[b * NCAND + sel] = ri[0];
            a[ri[0]] = -1e30f;
        }
        __syncthreads();
    }
}

// ---------------------------------------------------------------------------
// Kernel 4: autocorrelation score per (batch, candidate)
// grid = (NCAND, B). 256 threads. Coalesced: 16 lanes cover one row's 64 ch.
// ---------------------------------------------------------------------------
__global__ __launch_bounds__(256) void autocorr_kernel(const float* __restrict__ x)
{
    __shared__ float rs[T_LEN];
    __shared__ float qs[T_LEN];
    __shared__ float wacc[8];

    const int j   = blockIdx.x;
    const int b   = blockIdx.y;
    const int tid = threadIdx.x;

    const int idx = g_topidx[b * NCAND + j];
    const float pf = 4096.0f / (float)(idx + 1);
    int p = (int)floorf(pf);
    p = min(max(p, 2), T_LEN / 2);

    const float* xb = x + (size_t)b * T_LEN * C_CH;

    const int lane = tid & 31;
    const int warp = tid >> 5;
    const int sub  = lane >> 4;          // which of the warp's 2 rows
    const int ch   = (lane & 15) << 2;   // float offset within the row

    // r[t] = <x[t], x[t+p]> (0 when t+p >= T), q[t] = ||x[t]||^2
    for (int t = warp * 2 + sub; t < T_LEN; t += 16) {
        const float4 a = *(const float4*)(xb + (size_t)t * C_CH + ch);
        float q = a.x * a.x + a.y * a.y + a.z * a.z + a.w * a.w;
        float r = 0.0f;
        const int t2 = t + p;
        if (t2 < T_LEN) {
            const float4 bv = *(const float4*)(xb + (size_t)t2 * C_CH + ch);
            r = a.x * bv.x + a.y * bv.y + a.z * bv.z + a.w * bv.w;
        }
        #pragma unroll
        for (int o = 8; o > 0; o >>= 1) {
            q += __shfl_down_sync(0xffffffffu, q, o, 16);
            r += __shfl_down_sync(0xffffffffu, r, o, 16);
        }
        if ((lane & 15) == 0) { qs[t] = q; rs[t] = r; }
    }
    __syncthreads();

    // Per-segment cosine similarities; warp w handles segments w, w+8, ...
    const int nper = T_LEN / p;
    const int nseg = nper - 1;           // >= 1 since p <= T/2

    float wsum = 0.0f;
    for (int i = warp; i < nseg; i += 8) {
        const int s  = i * p;
        const int e  = s + p;
        const int e2 = e + p;
        float dot = 0.0f, na2 = 0.0f, nb2 = 0.0f;
        for (int t = s + lane; t < e; t += 32) { dot += rs[t]; na2 += qs[t]; }
        for (int t = e + lane; t < e2; t += 32) { nb2 += qs[t]; }
        #pragma unroll
        for (int o = 16; o > 0; o >>= 1) {
            dot += __shfl_down_sync(0xffffffffu, dot, o);
            na2 += __shfl_down_sync(0xffffffffu, na2, o);
            nb2 += __shfl_down_sync(0xffffffffu, nb2, o);
        }
        if (lane == 0) {
            const float na = sqrtf(fmaxf(na2, 0.0f));
            const float nb = sqrtf(fmaxf(nb2, 0.0f));
            wsum += dot / fmaxf(na * nb, 1e-8f);
        }
    }
    if (lane == 0) wacc[warp] = wsum;
    __syncthreads();
    if (tid == 0) {
        float total = 0.0f;
        #pragma unroll
        for (int w = 0; w < 8; w++) total += wacc[w];   // fixed order: deterministic
        g_scores[b * NCAND + j] = total / (float)nseg;
    }
}

// ---------------------------------------------------------------------------
// Kernel 5: final selection -> out = periods[64*3] ++ weights[64*3]
// ---------------------------------------------------------------------------
__global__ void select_kernel(float* __restrict__ out)
{
    const int b = blockIdx.x * blockDim.x + threadIdx.x;
    if (b >= B_SZ) return;

    int   pe[TOPK];
    float wt[TOPK];
    int cnt = 0;
    for (int j = 0; j < NCAND; j++) {
        const int idx = g_topidx[b * NCAND + j];
        const float pf  = 4096.0f / (float)(idx + 1);
        const float pfl = floorf(pf);
        const bool in_range     = (pf  >= 2.0f) && (pf  <= 2048.0f);
        const bool in_range_int = (pfl >= 2.0f) && (pfl <= 2048.0f);
        int pi = (int)pfl;
        pi = min(max(pi, 2), T_LEN / 2);
        const bool valid = in_range && in_range_int && (g_scores[b * NCAND + j] > 0.2f);
        if (valid && cnt < TOPK) { pe[cnt] = pi; wt[cnt] = 1.0f; cnt++; }
    }
    const int addp[3] = {1024, 1365, 2048};   // T//4, T//3, T//2 (int(T/1.5)=2730 > half)
    for (int j = cnt; j < TOPK; j++) {
        pe[j] = addp[min(j - cnt, 2)];
        wt[j] = 0.5f;
    }
    #pragma unroll
    for (int j = 0; j < TOPK; j++) {
        out[b * TOPK + j]                = (float)pe[j];
        out[B_SZ * TOPK + b * TOPK + j]  = wt[j];
    }
}

// ---------------------------------------------------------------------------
extern "C" void kernel_launch(void* const* d_in, const int* in_sizes, int n_in,
                              void* d_out, int out_size)
{
    const float* x  = (const float*)d_in[0];
    float* out = (float*)d_out;

    fft_kernel<<<B_SZ * 32, 256>>>(x);
    reduce_kernel<<<B_SZ, 256>>>();
    topk_kernel<<<B_SZ, 256>>>();
    autocorr_kernel<<<dim3(NCAND, B_SZ), 256>>>(x);
    select_kernel<<<1, 64>>>(out);
}

// round 4
// speedup vs baseline: 1.4645x; 1.0098x over previous
#include <cuda_runtime.h>
#include <cuda_bf16.h>
#include <math.h>

// Problem constants
#define T_LEN  4096
#define C_CH   64
#define B_SZ   64
#define NFREQ  2049            // T/2 + 1
#define FPAD   2052            // padded row for alignment
#define NCAND  6               // 2 * TOP_K
#define TOPK   3
#define LOG2T  12

// ---------------------------------------------------------------------------
// Scratch (device globals; no allocations allowed)
// ---------------------------------------------------------------------------
__device__ float  g_part[B_SZ * 32 * FPAD];  // per-(batch, channel-pair) amplitude sums
__device__ float  g_amps[B_SZ * FPAD];       // summed amplitudes per batch
__device__ int    g_topidx[B_SZ * NCAND];    // top-6 frequency indices per batch
__device__ float  g_scores[B_SZ * NCAND];    // autocorr scores per candidate
__device__ float2 g_tw[T_LEN / 2];           // twiddle table exp(-2*pi*i*e/4096)
__device__ float  g_q [B_SZ * T_LEN];        // ||x[b,t]||^2
__device__ float  g_r [B_SZ * NCAND * T_LEN];// <x[b,t], x[b,t+p_j]>

__device__ __forceinline__ float2 cmul(float2 a, float2 b) {
    return make_float2(a.x * b.x - a.y * b.y, a.x * b.y + a.y * b.x);
}

// W table holds exp(-2*pi*i*e/4096) for e in [0, 2048). For e in [2048, 4096):
// W^e = -W^(e-2048).  (We only ever need e < 3072.)
__device__ __forceinline__ float2 twget(const float2* __restrict__ W, int e) {
    float2 w = W[e & 2047];
    if (e & 2048) { w.x = -w.x; w.y = -w.y; }
    return w;
}

__device__ __forceinline__ int cand_period(int idx) {
    const float pf = 4096.0f / (float)(idx + 1);
    int p = (int)floorf(pf);
    return min(max(p, 2), T_LEN / 2);
}

// ---------------------------------------------------------------------------
// Kernel 0: build twiddle table once
// ---------------------------------------------------------------------------
__global__ __launch_bounds__(256) void twiddle_kernel()
{
    const int i = blockIdx.x * 256 + threadIdx.x;
    if (i < T_LEN / 2) {
        float ang = -6.283185307179586f * (float)i / (float)T_LEN;
        float s, c;
        sincosf(ang, &s, &c);
        g_tw[i] = make_float2(c, s);
    }
}

// ---------------------------------------------------------------------------
// Kernel 1: packed complex radix-4 FFT (2 real channels per FFT) + unpack
// grid = B*32 blocks, 256 threads. 48KB static smem.
// ---------------------------------------------------------------------------
__global__ __launch_bounds__(256) void fft_kernel(const float* __restrict__ x)
{
    __shared__ float2 z[T_LEN];     // 32 KB
    __shared__ float2 W[T_LEN / 2]; // 16 KB twiddles

    const int tid  = threadIdx.x;
    const int b    = blockIdx.x >> 5;
    const int pair = blockIdx.x & 31;
    const int c0   = pair * 2;

    // Twiddle table from global (coalesced, L2-hot)
    for (int i = tid; i < T_LEN / 2; i += 256)
        W[i] = g_tw[i];

    // Load with base-4 digit reversal (6 digits): z[rev4(t)] = (x[t,c0], x[t,c0+1])
    const float* xb = x + (size_t)b * T_LEN * C_CH;
    for (int t = tid; t < T_LEN; t += 256) {
        int tt = t, r = 0;
        #pragma unroll
        for (int i = 0; i < 6; i++) { r = (r << 2) | (tt & 3); tt >>= 2; }
        const float2 v = *(const float2*)(xb + (size_t)t * C_CH + c0);
        z[r] = v;
    }
    __syncthreads();

    // 6 radix-4 DIT stages
    #pragma unroll
    for (int s = 1; s <= 6; s++) {
        const int qtr  = 1 << (2 * (s - 1));
        const int twsh = 12 - 2 * s;
        #pragma unroll
        for (int u = 0; u < 4; u++) {
            const int j   = tid + u * 256;         // 1024 butterflies / stage
            const int grp = j >> (2 * (s - 1));
            const int pos = j & (qtr - 1);
            const int i0  = (grp << (2 * s)) + pos;
            const int tw  = pos << twsh;           // < 1024; 3*tw < 3072

            const float2 t0 = z[i0];
            const float2 t1 = cmul(z[i0 + qtr],     twget(W, tw));
            const float2 t2 = cmul(z[i0 + 2 * qtr], twget(W, 2 * tw));
            const float2 t3 = cmul(z[i0 + 3 * qtr], twget(W, 3 * tw));

            const float2 s02 = make_float2(t0.x + t2.x, t0.y + t2.y);
            const float2 d02 = make_float2(t0.x - t2.x, t0.y - t2.y);
            const float2 s13 = make_float2(t1.x + t3.x, t1.y + t3.y);
            const float2 d13 = make_float2(t1.x - t3.x, t1.y - t3.y);
            // -j * d13 = (d13.y, -d13.x)
            z[i0]           = make_float2(s02.x + s13.x, s02.y + s13.y);
            z[i0 + qtr]     = make_float2(d02.x + d13.y, d02.y - d13.x);
            z[i0 + 2 * qtr] = make_float2(s02.x - s13.x, s02.y - s13.y);
            z[i0 + 3 * qtr] = make_float2(d02.x - d13.y, d02.y + d13.x);
        }
        __syncthreads();
    }

    // Unpack Hermitian halves -> |X1[k]| + |X2[k]| for k in [0, 2048]
    float* out = g_part + (size_t)blockIdx.x * FPAD;
    for (int k = tid; k < NFREQ; k += 256) {
        const float2 a  = z[k];
        const float2 bm = z[(T_LEN - k) & (T_LEN - 1)];
        const float sr = 0.5f * (a.x + bm.x);
        const float si = 0.5f * (a.y - bm.y);
        const float dr = 0.5f * (a.x - bm.x);
        const float di = 0.5f * (a.y + bm.y);
        out[k] = sqrtf(sr * sr + si * si) + sqrtf(di * di + dr * dr);
    }
}

// ---------------------------------------------------------------------------
// Kernel 2: reduce 32 channel-pair partials per batch (deterministic order)
// ---------------------------------------------------------------------------
__global__ __launch_bounds__(256) void reduce_kernel()
{
    const int b = blockIdx.x;
    for (int k = threadIdx.x; k < NFREQ; k += 256) {
        float s = 0.0f;
        #pragma unroll 8
        for (int p = 0; p < 32; p++)
            s += g_part[(size_t)(b * 32 + p) * FPAD + k];
        g_amps[b * FPAD + k] = s;
    }
}

// ---------------------------------------------------------------------------
// Kernel 3: top-6 per batch (value desc, smaller index wins on ties)
// ---------------------------------------------------------------------------
__global__ __launch_bounds__(256) void topk_kernel()
{
    __shared__ float a[NFREQ];
    __shared__ float rv[256];
    __shared__ int   ri[256];

    const int b   = blockIdx.x;
    const int tid = threadIdx.x;

    for (int k = tid; k < NFREQ; k += 256) a[k] = g_amps[b * FPAD + k];
    __syncthreads();

    for (int sel = 0; sel < NCAND; sel++) {
        float bv = -1e30f;
        int   bi = 0x7fffffff;
        for (int k = tid; k < NFREQ; k += 256) {
            const float v = a[k];
            if (v > bv) { bv = v; bi = k; }   // ascending scan -> smallest idx on tie
        }
        rv[tid] = bv; ri[tid] = bi;
        __syncthreads();
        for (int s = 128; s > 0; s >>= 1) {
            if (tid < s) {
                const float v2 = rv[tid + s];
                const int   i2 = ri[tid + s];
                if (v2 > rv[tid] || (v2 == rv[tid] && i2 < ri[tid])) { rv[tid] = v2; ri[tid] = i2; }
            }
            __syncthreads();
        }
        if (tid == 0) {
            g_topidx[b * NCAND + sel] = ri[0];
            a[ri[0]] = -1e30f;
        }
        __syncthreads();
    }
}

// ---------------------------------------------------------------------------
// Kernel 4a: fill q[b][t] and r[b][j][t] for all 6 candidates at once.
// grid = (16 t-chunks, B). 256 threads, no smem -> high occupancy.
// Warp layout: 16 lanes cover one row's 64 channels (float4/lane), 2 rows/warp.
// ---------------------------------------------------------------------------
__global__ __launch_bounds__(256) void fill_kernel(const float* __restrict__ x)
{
    const int b   = blockIdx.y;
    const int t0  = blockIdx.x * 256;
    const int tid = threadIdx.x;

    int p[NCAND];
    #pragma unroll
    for (int j = 0; j < NCAND; j++)
        p[j] = cand_period(g_topidx[b * NCAND + j]);

    const float* xb = x + (size_t)b * T_LEN * C_CH;
    const int lane = tid & 31;
    const int warp = tid >> 5;
    const int sub  = lane >> 4;          // which of the warp's 2 rows
    const int ch   = (lane & 15) << 2;   // float offset within the row
    const bool wl  = (lane & 15) == 0;   // writer lane for this half-warp

    for (int i = 0; i < 16; i++) {
        const int t = t0 + i * 16 + warp * 2 + sub;
        const float4 a = *(const float4*)(xb + (size_t)t * C_CH + ch);

        float q = a.x * a.x + a.y * a.y + a.z * a.z + a.w * a.w;
        #pragma unroll
        for (int o = 8; o > 0; o >>= 1)
            q += __shfl_down_sync(0xffffffffu, q, o, 16);
        if (wl) g_q[b * T_LEN + t] = q;

        #pragma unroll
        for (int j = 0; j < NCAND; j++) {
            const int t2 = t + p[j];
            float r = 0.0f;
            if (t2 < T_LEN) {
                const float4 bv = *(const float4*)(xb + (size_t)t2 * C_CH + ch);
                r = a.x * bv.x + a.y * bv.y + a.z * bv.z + a.w * bv.w;
            }
            #pragma unroll
            for (int o = 8; o > 0; o >>= 1)
                r += __shfl_down_sync(0xffffffffu, r, o, 16);
            if (wl) g_r[(size_t)(b * NCAND + j) * T_LEN + t] = r;
        }
    }
}

// ---------------------------------------------------------------------------
// Kernel 4b: segment cosine score per (batch, candidate), from g_q / g_r.
// grid = (NCAND, B). 256 threads.
// ---------------------------------------------------------------------------
__global__ __launch_bounds__(256) void score_kernel()
{
    __shared__ float wacc[8];

    const int j   = blockIdx.x;
    const int b   = blockIdx.y;
    const int tid = threadIdx.x;

    const int p = cand_period(g_topidx[b * NCAND + j]);

    const float* rs = g_r + (size_t)(b * NCAND + j) * T_LEN;
    const float* qs = g_q + (size_t)b * T_LEN;

    const int nper = T_LEN / p;
    const int nseg = nper - 1;           // >= 1 since p <= T/2
    const int warp = tid >> 5;
    const int lane = tid & 31;

    float wsum = 0.0f;
    for (int i = warp; i < nseg; i += 8) {
        const int s  = i * p;
        const int e  = s + p;
        const int e2 = e + p;
        float dot = 0.0f, na2 = 0.0f, nb2 = 0.0f;
        for (int t = s + lane; t < e; t += 32) { dot += rs[t]; na2 += qs[t]; }
        for (int t = e + lane; t < e2; t += 32) { nb2 += qs[t]; }
        #pragma unroll
        for (int o = 16; o > 0; o >>= 1) {
            dot += __shfl_down_sync(0xffffffffu, dot, o);
            na2 += __shfl_down_sync(0xffffffffu, na2, o);
            nb2 += __shfl_down_sync(0xffffffffu, nb2, o);
        }
        if (lane == 0) {
            const float na = sqrtf(fmaxf(na2, 0.0f));
            const float nb = sqrtf(fmaxf(nb2, 0.0f));
            wsum += dot / fmaxf(na * nb, 1e-8f);
        }
    }
    if (lane == 0) wacc[warp] = wsum;
    __syncthreads();
    if (tid == 0) {
        float total = 0.0f;
        #pragma unroll
        for (int w = 0; w < 8; w++) total += wacc[w];   // fixed order: deterministic
        g_scores[b * NCAND + j] = total / (float)nseg;
    }
}

// ---------------------------------------------------------------------------
// Kernel 5: final selection -> out = periods[64*3] ++ weights[64*3]
// ---------------------------------------------------------------------------
__global__ void select_kernel(float* __restrict__ out)
{
    const int b = blockIdx.x * blockDim.x + threadIdx.x;
    if (b >= B_SZ) return;

    int   pe[TOPK];
    float wt[TOPK];
    int cnt = 0;
    for (int j = 0; j < NCAND; j++) {
        const int idx = g_topidx[b * NCAND + j];
        const float pf  = 4096.0f / (float)(idx + 1);
        const float pfl = floorf(pf);
        const bool in_range     = (pf  >= 2.0f) && (pf  <= 2048.0f);
        const bool in_range_int = (pfl >= 2.0f) && (pfl <= 2048.0f);
        int pi = (int)pfl;
        pi = min(max(pi, 2), T_LEN / 2);
        const bool valid = in_range && in_range_int && (g_scores[b * NCAND + j] > 0.2f);
        if (valid && cnt < TOPK) { pe[cnt] = pi; wt[cnt] = 1.0f; cnt++; }
    }
    const int addp[3] = {1024, 1365, 2048};   // T//4, T//3, T//2 (int(T/1.5)=2730 > half)
    for (int j = cnt; j < TOPK; j++) {
        pe[j] = addp[min(j - cnt, 2)];
        wt[j] = 0.5f;
    }
    #pragma unroll
    for (int j = 0; j < TOPK; j++) {
        out[b * TOPK + j]                = (float)pe[j];
        out[B_SZ * TOPK + b * TOPK + j]  = wt[j];
    }
}

// ---------------------------------------------------------------------------
extern "C" void kernel_launch(void* const* d_in, const int* in_sizes, int n_in,
                              void* d_out, int out_size)
{
    const float* x  = (const float*)d_in[0];
    float* out = (float*)d_out;

    twiddle_kernel<<<8, 256>>>();
    fft_kernel<<<B_SZ * 32, 256>>>(x);
    reduce_kernel<<<B_SZ, 256>>>();
    topk_kernel<<<B_SZ, 256>>>();
    fill_kernel<<<dim3(16, B_SZ), 256>>>(x);
    score_kernel<<<dim3(NCAND, B_SZ), 256>>>();
    select_kernel<<<1, 64>>>(out);
}